// round 13
// baseline (speedup 1.0000x reference)
#include <cuda_runtime.h>
#include <cuda_bf16.h>

#define BATCH       16
#define N_ROIS      1000
#define NUM_CLASSES 81
#define DET_MAX     100
#define MIN_CONF    0.7f
#define NMS_THRESH  0.3f
#define NB_Y        9              // 16*9 = 144 blocks (~1 per SM)
#define WPB         (32 * NB_Y)    // warps per batch = 288
#define ROI_PB      128            // ROIs handled per block (4 per warp)

typedef unsigned long long u64;
typedef unsigned int       u32;
typedef unsigned short     u16;

// Device-global scratch (zero-init at load; runner block resets counters so
// every graph replay sees identical initial state).
__device__ int    g_cnt[BATCH];
__device__ int    g_done[BATCH];
__device__ float4 g_boxA[BATCH * N_ROIS];   // y1,x1,y2,x2 (refined+clipped)
__device__ u64    g_key [BATCH * N_ROIS];   // (cls<<42)|(~scorebits<<10)|roi

// ---------------------------------------------------------------------------
// Warp argmax over 81 classes + (rare) refine/clip + stage to SHARED memory.
// ---------------------------------------------------------------------------
__device__ __forceinline__ void reduce_and_emit(
    float v0, float v1, float v2, int r, int b, int lane,
    const float* __restrict__ rois, const float* __restrict__ deltas,
    const float* __restrict__ window,
    int* st_cnt, float4* st_box, u64* st_key)
{
    float bv = v0; int bi = lane;
    if (v1 > bv) { bv = v1; bi = lane + 32; }
    if (v2 > bv) { bv = v2; bi = lane + 64; }
    #pragma unroll
    for (int off = 16; off > 0; off >>= 1) {
        const float ov = __shfl_xor_sync(0xffffffffu, bv, off);
        const int   oi = __shfl_xor_sync(0xffffffffu, bi, off);
        if (ov > bv || (ov == bv && oi < bi)) { bv = ov; bi = oi; }
    }
    if (lane == 0 && bi > 0 && bv >= MIN_CONF) {
        const float4 d4 = *(const float4*)(deltas +
            (((size_t)b * N_ROIS + r) * NUM_CLASSES + bi) * 4);
        const float4 rb = *(const float4*)(rois + ((size_t)b * N_ROIS + r) * 4);
        const float wy1 = window[b * 4 + 0];
        const float wx1 = window[b * 4 + 1];
        const float wy2 = window[b * 4 + 2];
        const float wx2 = window[b * 4 + 3];

        float h  = rb.z - rb.x;
        float w  = rb.w - rb.y;
        float cy = rb.x + 0.5f * h + (d4.x * 0.1f) * h;
        float cx = rb.y + 0.5f * w + (d4.y * 0.1f) * w;
        h = h * expf(d4.z * 0.2f);
        w = w * expf(d4.w * 0.2f);
        float y1 = cy - 0.5f * h;
        float x1 = cx - 0.5f * w;
        float y2 = y1 + h;
        float x2 = x1 + w;
        y1 = fminf(fmaxf(y1, wy1), wy2);
        x1 = fminf(fmaxf(x1, wx1), wx2);
        y2 = fminf(fmaxf(y2, wy1), wy2);
        x2 = fminf(fmaxf(x2, wx1), wx2);

        const int slot = atomicAdd(st_cnt, 1);          // SHARED atomic (cheap)
        st_box[slot] = make_float4(y1, x1, y2, x2);
        st_key[slot] =
            ((u64)(u32)bi << 42) |
            ((u64)(u32)(~__float_as_uint(bv)) << 10) |
            (u64)(u32)r;
    }
}

// ---------------------------------------------------------------------------
// Fused kernel: grid (BATCH, NB_Y). All blocks do a phase-1 slice (staging
// candidates in shared, ONE global atomic per block); the LAST block to
// finish for batch b runs phase 2 inline with its 1024 threads.
// ---------------------------------------------------------------------------
__global__ __launch_bounds__(1024, 1)
void det_fused_kernel(const float* __restrict__ probs,
                      const float* __restrict__ rois,
                      const float* __restrict__ deltas,
                      const float* __restrict__ window,
                      float* __restrict__ out)
{
    __shared__ float4        s_box[N_ROIS];        // 16 KB
    __shared__ u64           s_key[N_ROIS];        //  8 KB
    __shared__ u16           s_order[N_ROIS];      //  2 KB
    __shared__ unsigned char s_keep[N_ROIS];       //  1 KB
    __shared__ short         s_segb[NUM_CLASSES];
    __shared__ short         s_sege[NUM_CLASSES];
    __shared__ u16           s_klist[N_ROIS];      //  2 KB
    __shared__ u16           s_outidx[DET_MAX];
    // phase-1 staging
    __shared__ float4        st_box[ROI_PB];       //  2 KB
    __shared__ u64           st_key[ROI_PB];       //  1 KB
    __shared__ int           st_cnt, sBase;
    __shared__ int           sRun, sM, sK;

    const int b    = blockIdx.x;
    const int tid  = threadIdx.x;
    const int lane = tid & 31;
    const int warp = tid >> 5;

    if (tid == 0) st_cnt = 0;
    __syncthreads();

    // ======================= Phase 1: slice of argmax =======================
    {
        const int gw = blockIdx.y * 32 + warp;          // 0..287
        const float* base = probs + (size_t)b * N_ROIS * NUM_CLASSES;
        const int r0 = gw;
        const int r1 = gw + WPB;
        const int r2 = gw + 2 * WPB;
        const int r3 = gw + 3 * WPB;
        const bool h3   = (r3 < N_ROIS);
        const bool tail = (lane < NUM_CLASSES - 64);

        const float* p0 = base + (size_t)r0 * NUM_CLASSES;
        const float* p1 = base + (size_t)r1 * NUM_CLASSES;
        const float* p2 = base + (size_t)r2 * NUM_CLASSES;
        const float* p3 = base + (size_t)r3 * NUM_CLASSES;

        const float a0 = p0[lane];
        const float a1 = p1[lane];
        const float a2 = p2[lane];
        const float a3 = h3 ? p3[lane] : -1e30f;
        const float b0 = p0[lane + 32];
        const float b1 = p1[lane + 32];
        const float b2 = p2[lane + 32];
        const float b3 = h3 ? p3[lane + 32] : -1e30f;
        const float c0 = tail ? p0[lane + 64] : -1e30f;
        const float c1 = tail ? p1[lane + 64] : -1e30f;
        const float c2 = tail ? p2[lane + 64] : -1e30f;
        const float c3 = (h3 && tail) ? p3[lane + 64] : -1e30f;

        reduce_and_emit(a0, b0, c0, r0, b, lane, rois, deltas, window,
                        &st_cnt, st_box, st_key);
        reduce_and_emit(a1, b1, c1, r1, b, lane, rois, deltas, window,
                        &st_cnt, st_box, st_key);
        reduce_and_emit(a2, b2, c2, r2, b, lane, rois, deltas, window,
                        &st_cnt, st_box, st_key);
        if (h3) reduce_and_emit(a3, b3, c3, r3, b, lane, rois, deltas, window,
                                &st_cnt, st_box, st_key);
    }
    __syncthreads();

    // ---- publish staged candidates: ONE global atomic per block ------------
    const int cnt = st_cnt;
    if (tid == 0) sBase = atomicAdd(&g_cnt[b], cnt);
    __syncthreads();
    const int basep = sBase;
    for (int t = tid; t < cnt; t += 1024) {
        g_boxA[b * N_ROIS + basep + t] = st_box[t];
        g_key [b * N_ROIS + basep + t] = st_key[t];
    }
    __syncthreads();

    // =================== last-block election for batch b ====================
    if (tid == 0) {
        __threadfence();                        // release this block's records
        const int old = atomicAdd(&g_done[b], 1);
        sRun = (old == NB_Y - 1) ? 1 : 0;
        if (sRun) {
            sM = atomicAdd(&g_cnt[b], 0);       // L2 read on acquire side
            sK = 0;
        }
    }
    __syncthreads();
    if (!sRun) return;
    const int M = sM;

    // ======================= Phase 2 (1024 threads) =========================
    for (int t = tid; t < M; t += 1024) {
        s_box[t] = g_boxA[b * N_ROIS + t];
        s_key[t] = g_key [b * N_ROIS + t];
    }
    if (tid < NUM_CLASSES) { s_segb[tid] = 0; s_sege[tid] = 0; }
    __syncthreads();
    if (tid == 0) { g_cnt[b] = 0; g_done[b] = 0; }   // reset for next replay

    // ---- rank sort by key (cls asc, score desc, roi asc); keys unique ------
    for (int t = tid; t < M; t += 1024) {
        const u64 kt = s_key[t];
        int rank = 0;
        for (int j = 0; j < M; ++j) rank += (s_key[j] < kt);
        s_order[rank] = (u16)t;
    }
    __syncthreads();

    // ---- class segment boundaries ------------------------------------------
    for (int p = tid; p < M; p += 1024) {
        const int c = (int)(s_key[s_order[p]] >> 42);
        if (p == 0     || (int)(s_key[s_order[p - 1]] >> 42) != c) s_segb[c] = (short)p;
        if (p == M - 1 || (int)(s_key[s_order[p + 1]] >> 42) != c) s_sege[c] = (short)(p + 1);
    }
    __syncthreads();

    // ---- per-class greedy NMS: one warp per class --------------------------
    for (int c = 1 + warp; c < NUM_CLASSES; c += 32) {
        const int beg = s_segb[c];
        const int end = s_sege[c];
        int keptc = 0;
        for (int p = beg; p < end; ++p) {
            const float4 bi4 = s_box[s_order[p]];        // broadcast
            const float area_i = (bi4.z - bi4.x) * (bi4.w - bi4.y);
            bool sup = false;
            for (int q = beg + lane; q < p; q += 32) {
                if (!s_keep[q]) continue;                // only kept suppress
                const float4 bj = s_box[s_order[q]];
                const float yy1 = fmaxf(bi4.x, bj.x);
                const float xx1 = fmaxf(bi4.y, bj.y);
                const float yy2 = fminf(bi4.z, bj.z);
                const float xx2 = fminf(bi4.w, bj.w);
                const float inter = fmaxf(yy2 - yy1, 0.0f) * fmaxf(xx2 - xx1, 0.0f);
                const float area_j = (bj.z - bj.x) * (bj.w - bj.y);
                const float uni = fmaxf(area_i + area_j - inter, 1e-10f);
                if (inter / uni > NMS_THRESH) sup = true;
            }
            sup = __any_sync(0xffffffffu, sup);
            const bool kp = !sup && (keptc < DET_MAX);
            if (lane == 0) s_keep[p] = kp ? 1 : 0;
            keptc += kp ? 1 : 0;
            __syncwarp();            // publish s_keep[p] before next item
        }
    }
    __syncthreads();

    // ---- compact kept (order irrelevant; final rank restores determinism) --
    for (int p = tid; p < M; p += 1024)
        if (s_keep[p]) s_klist[atomicAdd(&sK, 1)] = s_order[p];
    __syncthreads();
    const int K = sK;

    // ---- final rank among kept by (score desc, roi asc) = low 42 key bits --
    const u64 SMASK = ((u64)1 << 42) - 1;
    for (int t = tid; t < K; t += 1024) {
        const u64 kt = s_key[s_klist[t]] & SMASK;
        int rank = 0;
        for (int j = 0; j < K; ++j) rank += ((s_key[s_klist[j]] & SMASK) < kt);
        if (rank < DET_MAX) s_outidx[rank] = s_klist[t];
    }
    __syncthreads();

    // ---- write [100, 6] output, zero padded --------------------------------
    const int nk = (K < DET_MAX) ? K : DET_MAX;
    float* o = out + (size_t)b * DET_MAX * 6;
    for (int t = tid; t < DET_MAX; t += 1024) {
        if (t < nk) {
            const int ci = s_outidx[t];
            const float4 bb = s_box[ci];
            const u64   key = s_key[ci];
            o[t * 6 + 0] = bb.x;
            o[t * 6 + 1] = bb.y;
            o[t * 6 + 2] = bb.z;
            o[t * 6 + 3] = bb.w;
            o[t * 6 + 4] = (float)(int)(key >> 42);
            o[t * 6 + 5] = __uint_as_float(~(u32)((key >> 10) & 0xFFFFFFFFu));
        } else {
            #pragma unroll
            for (int k = 0; k < 6; ++k) o[t * 6 + k] = 0.0f;
        }
    }
}

extern "C" void kernel_launch(void* const* d_in, const int* in_sizes, int n_in,
                              void* d_out, int out_size)
{
    const float* rois   = nullptr;
    const float* probs  = nullptr;
    const float* deltas = nullptr;
    const float* window = nullptr;
    for (int i = 0; i < n_in; ++i) {
        switch (in_sizes[i]) {
            case BATCH * N_ROIS * 4:                rois   = (const float*)d_in[i]; break;
            case BATCH * N_ROIS * NUM_CLASSES:      probs  = (const float*)d_in[i]; break;
            case BATCH * N_ROIS * NUM_CLASSES * 4:  deltas = (const float*)d_in[i]; break;
            case BATCH * 4:                         window = (const float*)d_in[i]; break;
        }
    }
    det_fused_kernel<<<dim3(BATCH, NB_Y), 1024>>>(
        probs, rois, deltas, window, (float*)d_out);
}

// round 14
// speedup vs baseline: 1.0175x; 1.0175x over previous
#include <cuda_runtime.h>
#include <cuda_bf16.h>

#define BATCH       16
#define N_ROIS      1000
#define NUM_CLASSES 81
#define DET_MAX     100
#define MIN_CONF    0.7f
#define NMS_THRESH  0.3f
#define NB_Y        9              // 16*9 = 144 blocks (~1 per SM)
#define WPB         (32 * NB_Y)    // warps per batch = 288
#define ROI_PB      128            // ROIs handled per block (4 per warp)

typedef unsigned long long u64;
typedef unsigned int       u32;
typedef unsigned short     u16;

// Device-global scratch (zero-init at load; runner block resets counters so
// every graph replay sees identical initial state).
__device__ int    g_cnt[BATCH];
__device__ int    g_done[BATCH];
__device__ float4 g_boxA[BATCH * N_ROIS];   // y1,x1,y2,x2 (refined+clipped)
__device__ u64    g_key [BATCH * N_ROIS];   // (cls<<42)|(~scorebits<<10)|roi

// ---------------------------------------------------------------------------
// Warp argmax over 81 classes + (rare) refine/clip + stage to SHARED memory.
// ---------------------------------------------------------------------------
__device__ __forceinline__ void reduce_and_emit(
    float v0, float v1, float v2, int r, int b, int lane,
    const float* __restrict__ rois, const float* __restrict__ deltas,
    const float* __restrict__ window,
    int* st_cnt, float4* st_box, u64* st_key)
{
    float bv = v0; int bi = lane;
    if (v1 > bv) { bv = v1; bi = lane + 32; }
    if (v2 > bv) { bv = v2; bi = lane + 64; }
    #pragma unroll
    for (int off = 16; off > 0; off >>= 1) {
        const float ov = __shfl_xor_sync(0xffffffffu, bv, off);
        const int   oi = __shfl_xor_sync(0xffffffffu, bi, off);
        if (ov > bv || (ov == bv && oi < bi)) { bv = ov; bi = oi; }
    }
    if (lane == 0 && bi > 0 && bv >= MIN_CONF) {
        const float4 d4 = *(const float4*)(deltas +
            (((size_t)b * N_ROIS + r) * NUM_CLASSES + bi) * 4);
        const float4 rb = *(const float4*)(rois + ((size_t)b * N_ROIS + r) * 4);
        const float wy1 = window[b * 4 + 0];
        const float wx1 = window[b * 4 + 1];
        const float wy2 = window[b * 4 + 2];
        const float wx2 = window[b * 4 + 3];

        float h  = rb.z - rb.x;
        float w  = rb.w - rb.y;
        float cy = rb.x + 0.5f * h + (d4.x * 0.1f) * h;
        float cx = rb.y + 0.5f * w + (d4.y * 0.1f) * w;
        h = h * expf(d4.z * 0.2f);
        w = w * expf(d4.w * 0.2f);
        float y1 = cy - 0.5f * h;
        float x1 = cx - 0.5f * w;
        float y2 = y1 + h;
        float x2 = x1 + w;
        y1 = fminf(fmaxf(y1, wy1), wy2);
        x1 = fminf(fmaxf(x1, wx1), wx2);
        y2 = fminf(fmaxf(y2, wy1), wy2);
        x2 = fminf(fmaxf(x2, wx1), wx2);

        const int slot = atomicAdd(st_cnt, 1);          // SHARED atomic (cheap)
        st_box[slot] = make_float4(y1, x1, y2, x2);
        st_key[slot] =
            ((u64)(u32)bi << 42) |
            ((u64)(u32)(~__float_as_uint(bv)) << 10) |
            (u64)(u32)r;
    }
}

// ---------------------------------------------------------------------------
// Fused kernel: grid (BATCH, NB_Y). All blocks do a phase-1 slice (staging
// candidates in shared, ONE global atomic per block); the LAST block to
// finish for batch b runs phase 2 inline with its 1024 threads.
// ---------------------------------------------------------------------------
__global__ __launch_bounds__(1024, 1)
void det_fused_kernel(const float* __restrict__ probs,
                      const float* __restrict__ rois,
                      const float* __restrict__ deltas,
                      const float* __restrict__ window,
                      float* __restrict__ out)
{
    __shared__ float4        s_box[N_ROIS];        // 16 KB
    __shared__ u64           s_key[N_ROIS];        //  8 KB
    __shared__ u16           s_order[N_ROIS];      //  2 KB
    __shared__ unsigned char s_keep[N_ROIS];       //  1 KB
    __shared__ short         s_segb[NUM_CLASSES];
    __shared__ short         s_sege[NUM_CLASSES];
    __shared__ u16           s_klist[N_ROIS];      //  2 KB
    __shared__ u16           s_outidx[DET_MAX];
    // phase-1 staging
    __shared__ float4        st_box[ROI_PB];       //  2 KB
    __shared__ u64           st_key[ROI_PB];       //  1 KB
    __shared__ int           st_cnt, sBase;
    __shared__ int           sRun, sM, sK;

    const int b    = blockIdx.x;
    const int tid  = threadIdx.x;
    const int lane = tid & 31;
    const int warp = tid >> 5;

    if (tid == 0) st_cnt = 0;
    __syncthreads();

    // ======================= Phase 1: slice of argmax =======================
    {
        const int gw = blockIdx.y * 32 + warp;          // 0..287
        const float* base = probs + (size_t)b * N_ROIS * NUM_CLASSES;
        const int r0 = gw;
        const int r1 = gw + WPB;
        const int r2 = gw + 2 * WPB;
        const int r3 = gw + 3 * WPB;
        const bool h3   = (r3 < N_ROIS);
        const bool tail = (lane < NUM_CLASSES - 64);

        const float* p0 = base + (size_t)r0 * NUM_CLASSES;
        const float* p1 = base + (size_t)r1 * NUM_CLASSES;
        const float* p2 = base + (size_t)r2 * NUM_CLASSES;
        const float* p3 = base + (size_t)r3 * NUM_CLASSES;

        const float a0 = p0[lane];
        const float a1 = p1[lane];
        const float a2 = p2[lane];
        const float a3 = h3 ? p3[lane] : -1e30f;
        const float b0 = p0[lane + 32];
        const float b1 = p1[lane + 32];
        const float b2 = p2[lane + 32];
        const float b3 = h3 ? p3[lane + 32] : -1e30f;
        const float c0 = tail ? p0[lane + 64] : -1e30f;
        const float c1 = tail ? p1[lane + 64] : -1e30f;
        const float c2 = tail ? p2[lane + 64] : -1e30f;
        const float c3 = (h3 && tail) ? p3[lane + 64] : -1e30f;

        reduce_and_emit(a0, b0, c0, r0, b, lane, rois, deltas, window,
                        &st_cnt, st_box, st_key);
        reduce_and_emit(a1, b1, c1, r1, b, lane, rois, deltas, window,
                        &st_cnt, st_box, st_key);
        reduce_and_emit(a2, b2, c2, r2, b, lane, rois, deltas, window,
                        &st_cnt, st_box, st_key);
        if (h3) reduce_and_emit(a3, b3, c3, r3, b, lane, rois, deltas, window,
                                &st_cnt, st_box, st_key);
    }
    __syncthreads();

    // ---- publish staged candidates: ONE global atomic per block ------------
    const int cnt = st_cnt;
    if (tid == 0) sBase = atomicAdd(&g_cnt[b], cnt);
    __syncthreads();
    const int basep = sBase;
    for (int t = tid; t < cnt; t += 1024) {
        g_boxA[b * N_ROIS + basep + t] = st_box[t];
        g_key [b * N_ROIS + basep + t] = st_key[t];
    }
    __syncthreads();

    // =================== last-block election for batch b ====================
    if (tid == 0) {
        __threadfence();                        // release this block's records
        const int old = atomicAdd(&g_done[b], 1);
        sRun = (old == NB_Y - 1) ? 1 : 0;
        if (sRun) {
            sM = atomicAdd(&g_cnt[b], 0);       // L2 read on acquire side
            sK = 0;
        }
    }
    __syncthreads();
    if (!sRun) return;
    const int M = sM;

    // ======================= Phase 2 (1024 threads) =========================
    for (int t = tid; t < M; t += 1024) {
        s_box[t] = g_boxA[b * N_ROIS + t];
        s_key[t] = g_key [b * N_ROIS + t];
    }
    if (tid < NUM_CLASSES) { s_segb[tid] = 0; s_sege[tid] = 0; }
    __syncthreads();
    if (tid == 0) { g_cnt[b] = 0; g_done[b] = 0; }   // reset for next replay

    // ---- rank sort by key (cls asc, score desc, roi asc); keys unique ------
    for (int t = tid; t < M; t += 1024) {
        const u64 kt = s_key[t];
        int rank = 0;
        for (int j = 0; j < M; ++j) rank += (s_key[j] < kt);
        s_order[rank] = (u16)t;
    }
    __syncthreads();

    // ---- class segment boundaries ------------------------------------------
    for (int p = tid; p < M; p += 1024) {
        const int c = (int)(s_key[s_order[p]] >> 42);
        if (p == 0     || (int)(s_key[s_order[p - 1]] >> 42) != c) s_segb[c] = (short)p;
        if (p == M - 1 || (int)(s_key[s_order[p + 1]] >> 42) != c) s_sege[c] = (short)(p + 1);
    }
    __syncthreads();

    // ---- per-class greedy NMS: one warp per class --------------------------
    for (int c = 1 + warp; c < NUM_CLASSES; c += 32) {
        const int beg = s_segb[c];
        const int end = s_sege[c];
        int keptc = 0;
        for (int p = beg; p < end; ++p) {
            const float4 bi4 = s_box[s_order[p]];        // broadcast
            const float area_i = (bi4.z - bi4.x) * (bi4.w - bi4.y);
            bool sup = false;
            for (int q = beg + lane; q < p; q += 32) {
                if (!s_keep[q]) continue;                // only kept suppress
                const float4 bj = s_box[s_order[q]];
                const float yy1 = fmaxf(bi4.x, bj.x);
                const float xx1 = fmaxf(bi4.y, bj.y);
                const float yy2 = fminf(bi4.z, bj.z);
                const float xx2 = fminf(bi4.w, bj.w);
                const float inter = fmaxf(yy2 - yy1, 0.0f) * fmaxf(xx2 - xx1, 0.0f);
                const float area_j = (bj.z - bj.x) * (bj.w - bj.y);
                const float uni = fmaxf(area_i + area_j - inter, 1e-10f);
                if (inter / uni > NMS_THRESH) sup = true;
            }
            sup = __any_sync(0xffffffffu, sup);
            const bool kp = !sup && (keptc < DET_MAX);
            if (lane == 0) s_keep[p] = kp ? 1 : 0;
            keptc += kp ? 1 : 0;
            __syncwarp();            // publish s_keep[p] before next item
        }
    }
    __syncthreads();

    // ---- compact kept (order irrelevant; final rank restores determinism) --
    for (int p = tid; p < M; p += 1024)
        if (s_keep[p]) s_klist[atomicAdd(&sK, 1)] = s_order[p];
    __syncthreads();
    const int K = sK;

    // ---- final rank among kept by (score desc, roi asc) = low 42 key bits --
    const u64 SMASK = ((u64)1 << 42) - 1;
    for (int t = tid; t < K; t += 1024) {
        const u64 kt = s_key[s_klist[t]] & SMASK;
        int rank = 0;
        for (int j = 0; j < K; ++j) rank += ((s_key[s_klist[j]] & SMASK) < kt);
        if (rank < DET_MAX) s_outidx[rank] = s_klist[t];
    }
    __syncthreads();

    // ---- write [100, 6] output, zero padded --------------------------------
    const int nk = (K < DET_MAX) ? K : DET_MAX;
    float* o = out + (size_t)b * DET_MAX * 6;
    for (int t = tid; t < DET_MAX; t += 1024) {
        if (t < nk) {
            const int ci = s_outidx[t];
            const float4 bb = s_box[ci];
            const u64   key = s_key[ci];
            o[t * 6 + 0] = bb.x;
            o[t * 6 + 1] = bb.y;
            o[t * 6 + 2] = bb.z;
            o[t * 6 + 3] = bb.w;
            o[t * 6 + 4] = (float)(int)(key >> 42);
            o[t * 6 + 5] = __uint_as_float(~(u32)((key >> 10) & 0xFFFFFFFFu));
        } else {
            #pragma unroll
            for (int k = 0; k < 6; ++k) o[t * 6 + k] = 0.0f;
        }
    }
}

extern "C" void kernel_launch(void* const* d_in, const int* in_sizes, int n_in,
                              void* d_out, int out_size)
{
    const float* rois   = nullptr;
    const float* probs  = nullptr;
    const float* deltas = nullptr;
    const float* window = nullptr;
    for (int i = 0; i < n_in; ++i) {
        switch (in_sizes[i]) {
            case BATCH * N_ROIS * 4:                rois   = (const float*)d_in[i]; break;
            case BATCH * N_ROIS * NUM_CLASSES:      probs  = (const float*)d_in[i]; break;
            case BATCH * N_ROIS * NUM_CLASSES * 4:  deltas = (const float*)d_in[i]; break;
            case BATCH * 4:                         window = (const float*)d_in[i]; break;
        }
    }
    det_fused_kernel<<<dim3(BATCH, NB_Y), 1024>>>(
        probs, rois, deltas, window, (float*)d_out);
}

// round 15
// speedup vs baseline: 1.0304x; 1.0127x over previous
#include <cuda_runtime.h>
#include <cuda_bf16.h>

#define BATCH       16
#define N_ROIS      1000
#define NUM_CLASSES 81
#define DET_MAX     100
#define MIN_CONF    0.7f
#define NMS_THRESH  0.3f
#define NB_Y        9              // 16*9 = 144 blocks (~1 per SM)
#define WPB         (32 * NB_Y)    // warps per batch = 288
#define ROI_PB      128            // ROIs handled per block (4 per warp)

typedef unsigned long long u64;
typedef unsigned int       u32;
typedef unsigned short     u16;

// Device-global scratch (zero-init at load; runner block resets counters so
// every graph replay sees identical initial state).
__device__ int    g_cnt[BATCH];
__device__ int    g_done[BATCH];
__device__ float4 g_boxA[BATCH * N_ROIS];   // y1,x1,y2,x2 (refined+clipped)
__device__ u64    g_key [BATCH * N_ROIS];   // (cls<<42)|(~scorebits<<10)|roi

// ---------------------------------------------------------------------------
// Warp argmax over 81 classes + (rare) refine/clip + stage to SHARED memory.
// ---------------------------------------------------------------------------
__device__ __forceinline__ void reduce_and_emit(
    float v0, float v1, float v2, int r, int b, int lane,
    const float* __restrict__ rois, const float* __restrict__ deltas,
    const float* __restrict__ window,
    int* st_cnt, float4* st_box, u64* st_key)
{
    float bv = v0; int bi = lane;
    if (v1 > bv) { bv = v1; bi = lane + 32; }
    if (v2 > bv) { bv = v2; bi = lane + 64; }
    #pragma unroll
    for (int off = 16; off > 0; off >>= 1) {
        const float ov = __shfl_xor_sync(0xffffffffu, bv, off);
        const int   oi = __shfl_xor_sync(0xffffffffu, bi, off);
        if (ov > bv || (ov == bv && oi < bi)) { bv = ov; bi = oi; }
    }
    if (lane == 0 && bi > 0 && bv >= MIN_CONF) {
        const float4 d4 = *(const float4*)(deltas +
            (((size_t)b * N_ROIS + r) * NUM_CLASSES + bi) * 4);
        const float4 rb = *(const float4*)(rois + ((size_t)b * N_ROIS + r) * 4);
        const float wy1 = window[b * 4 + 0];
        const float wx1 = window[b * 4 + 1];
        const float wy2 = window[b * 4 + 2];
        const float wx2 = window[b * 4 + 3];

        float h  = rb.z - rb.x;
        float w  = rb.w - rb.y;
        float cy = rb.x + 0.5f * h + (d4.x * 0.1f) * h;
        float cx = rb.y + 0.5f * w + (d4.y * 0.1f) * w;
        h = h * expf(d4.z * 0.2f);
        w = w * expf(d4.w * 0.2f);
        float y1 = cy - 0.5f * h;
        float x1 = cx - 0.5f * w;
        float y2 = y1 + h;
        float x2 = x1 + w;
        y1 = fminf(fmaxf(y1, wy1), wy2);
        x1 = fminf(fmaxf(x1, wx1), wx2);
        y2 = fminf(fmaxf(y2, wy1), wy2);
        x2 = fminf(fmaxf(x2, wx1), wx2);

        const int slot = atomicAdd(st_cnt, 1);          // SHARED atomic (cheap)
        st_box[slot] = make_float4(y1, x1, y2, x2);
        st_key[slot] =
            ((u64)(u32)bi << 42) |
            ((u64)(u32)(~__float_as_uint(bv)) << 10) |
            (u64)(u32)r;
    }
}

// ---------------------------------------------------------------------------
// Fused kernel: grid (BATCH, NB_Y). All blocks do a phase-1 slice (staging
// candidates in shared, ONE global atomic per block); the LAST block to
// finish for batch b runs phase 2 inline with its 1024 threads.
// ---------------------------------------------------------------------------
__global__ __launch_bounds__(1024, 1)
void det_fused_kernel(const float* __restrict__ probs,
                      const float* __restrict__ rois,
                      const float* __restrict__ deltas,
                      const float* __restrict__ window,
                      float* __restrict__ out)
{
    __shared__ float4        s_box[N_ROIS];        // 16 KB
    __shared__ u64           s_key[N_ROIS];        //  8 KB
    __shared__ u16           s_order[N_ROIS];      //  2 KB
    __shared__ unsigned char s_keep[N_ROIS];       //  1 KB
    __shared__ short         s_segb[NUM_CLASSES];
    __shared__ short         s_sege[NUM_CLASSES];
    __shared__ u16           s_klist[N_ROIS];      //  2 KB
    __shared__ u16           s_outidx[DET_MAX];
    // phase-1 staging
    __shared__ float4        st_box[ROI_PB];       //  2 KB
    __shared__ u64           st_key[ROI_PB];       //  1 KB
    __shared__ int           st_cnt, sBase;
    __shared__ int           sRun, sM, sK;

    const int b    = blockIdx.x;
    const int tid  = threadIdx.x;
    const int lane = tid & 31;
    const int warp = tid >> 5;

    if (tid == 0) st_cnt = 0;
    __syncthreads();

    // ======================= Phase 1: slice of argmax =======================
    {
        const int gw = blockIdx.y * 32 + warp;          // 0..287
        const float* base = probs + (size_t)b * N_ROIS * NUM_CLASSES;
        const int r0 = gw;
        const int r1 = gw + WPB;
        const int r2 = gw + 2 * WPB;
        const int r3 = gw + 3 * WPB;
        const bool h3   = (r3 < N_ROIS);
        const bool tail = (lane < NUM_CLASSES - 64);

        const float* p0 = base + (size_t)r0 * NUM_CLASSES;
        const float* p1 = base + (size_t)r1 * NUM_CLASSES;
        const float* p2 = base + (size_t)r2 * NUM_CLASSES;
        const float* p3 = base + (size_t)r3 * NUM_CLASSES;

        const float a0 = p0[lane];
        const float a1 = p1[lane];
        const float a2 = p2[lane];
        const float a3 = h3 ? p3[lane] : -1e30f;
        const float b0 = p0[lane + 32];
        const float b1 = p1[lane + 32];
        const float b2 = p2[lane + 32];
        const float b3 = h3 ? p3[lane + 32] : -1e30f;
        const float c0 = tail ? p0[lane + 64] : -1e30f;
        const float c1 = tail ? p1[lane + 64] : -1e30f;
        const float c2 = tail ? p2[lane + 64] : -1e30f;
        const float c3 = (h3 && tail) ? p3[lane + 64] : -1e30f;

        reduce_and_emit(a0, b0, c0, r0, b, lane, rois, deltas, window,
                        &st_cnt, st_box, st_key);
        reduce_and_emit(a1, b1, c1, r1, b, lane, rois, deltas, window,
                        &st_cnt, st_box, st_key);
        reduce_and_emit(a2, b2, c2, r2, b, lane, rois, deltas, window,
                        &st_cnt, st_box, st_key);
        if (h3) reduce_and_emit(a3, b3, c3, r3, b, lane, rois, deltas, window,
                                &st_cnt, st_box, st_key);
    }
    __syncthreads();

    // ---- publish staged candidates: ONE global atomic per block ------------
    const int cnt = st_cnt;
    if (tid == 0) sBase = atomicAdd(&g_cnt[b], cnt);
    __syncthreads();
    const int basep = sBase;
    for (int t = tid; t < cnt; t += 1024) {
        g_boxA[b * N_ROIS + basep + t] = st_box[t];
        g_key [b * N_ROIS + basep + t] = st_key[t];
    }
    __syncthreads();

    // =================== last-block election for batch b ====================
    if (tid == 0) {
        __threadfence();                        // release this block's records
        const int old = atomicAdd(&g_done[b], 1);
        sRun = (old == NB_Y - 1) ? 1 : 0;
        if (sRun) {
            sM = atomicAdd(&g_cnt[b], 0);       // L2 read on acquire side
            sK = 0;
        }
    }
    __syncthreads();
    if (!sRun) return;
    const int M = sM;

    // ======================= Phase 2 (1024 threads) =========================
    for (int t = tid; t < M; t += 1024) {
        s_box[t] = g_boxA[b * N_ROIS + t];
        s_key[t] = g_key [b * N_ROIS + t];
    }
    if (tid < NUM_CLASSES) { s_segb[tid] = 0; s_sege[tid] = 0; }
    __syncthreads();
    if (tid == 0) { g_cnt[b] = 0; g_done[b] = 0; }   // reset for next replay

    // ---- rank sort by key (cls asc, score desc, roi asc); keys unique ------
    for (int t = tid; t < M; t += 1024) {
        const u64 kt = s_key[t];
        int rank = 0;
        for (int j = 0; j < M; ++j) rank += (s_key[j] < kt);
        s_order[rank] = (u16)t;
    }
    __syncthreads();

    // ---- class segment boundaries ------------------------------------------
    for (int p = tid; p < M; p += 1024) {
        const int c = (int)(s_key[s_order[p]] >> 42);
        if (p == 0     || (int)(s_key[s_order[p - 1]] >> 42) != c) s_segb[c] = (short)p;
        if (p == M - 1 || (int)(s_key[s_order[p + 1]] >> 42) != c) s_sege[c] = (short)(p + 1);
    }
    __syncthreads();

    // ---- per-class greedy NMS: one warp per class --------------------------
    for (int c = 1 + warp; c < NUM_CLASSES; c += 32) {
        const int beg = s_segb[c];
        const int end = s_sege[c];
        int keptc = 0;
        for (int p = beg; p < end; ++p) {
            const float4 bi4 = s_box[s_order[p]];        // broadcast
            const float area_i = (bi4.z - bi4.x) * (bi4.w - bi4.y);
            bool sup = false;
            for (int q = beg + lane; q < p; q += 32) {
                if (!s_keep[q]) continue;                // only kept suppress
                const float4 bj = s_box[s_order[q]];
                const float yy1 = fmaxf(bi4.x, bj.x);
                const float xx1 = fmaxf(bi4.y, bj.y);
                const float yy2 = fminf(bi4.z, bj.z);
                const float xx2 = fminf(bi4.w, bj.w);
                const float inter = fmaxf(yy2 - yy1, 0.0f) * fmaxf(xx2 - xx1, 0.0f);
                const float area_j = (bj.z - bj.x) * (bj.w - bj.y);
                const float uni = fmaxf(area_i + area_j - inter, 1e-10f);
                if (inter / uni > NMS_THRESH) sup = true;
            }
            sup = __any_sync(0xffffffffu, sup);
            const bool kp = !sup && (keptc < DET_MAX);
            if (lane == 0) s_keep[p] = kp ? 1 : 0;
            keptc += kp ? 1 : 0;
            __syncwarp();            // publish s_keep[p] before next item
        }
    }
    __syncthreads();

    // ---- compact kept (order irrelevant; final rank restores determinism) --
    for (int p = tid; p < M; p += 1024)
        if (s_keep[p]) s_klist[atomicAdd(&sK, 1)] = s_order[p];
    __syncthreads();
    const int K = sK;

    // ---- final rank among kept by (score desc, roi asc) = low 42 key bits --
    const u64 SMASK = ((u64)1 << 42) - 1;
    for (int t = tid; t < K; t += 1024) {
        const u64 kt = s_key[s_klist[t]] & SMASK;
        int rank = 0;
        for (int j = 0; j < K; ++j) rank += ((s_key[s_klist[j]] & SMASK) < kt);
        if (rank < DET_MAX) s_outidx[rank] = s_klist[t];
    }
    __syncthreads();

    // ---- write [100, 6] output, zero padded --------------------------------
    const int nk = (K < DET_MAX) ? K : DET_MAX;
    float* o = out + (size_t)b * DET_MAX * 6;
    for (int t = tid; t < DET_MAX; t += 1024) {
        if (t < nk) {
            const int ci = s_outidx[t];
            const float4 bb = s_box[ci];
            const u64   key = s_key[ci];
            o[t * 6 + 0] = bb.x;
            o[t * 6 + 1] = bb.y;
            o[t * 6 + 2] = bb.z;
            o[t * 6 + 3] = bb.w;
            o[t * 6 + 4] = (float)(int)(key >> 42);
            o[t * 6 + 5] = __uint_as_float(~(u32)((key >> 10) & 0xFFFFFFFFu));
        } else {
            #pragma unroll
            for (int k = 0; k < 6; ++k) o[t * 6 + k] = 0.0f;
        }
    }
}

extern "C" void kernel_launch(void* const* d_in, const int* in_sizes, int n_in,
                              void* d_out, int out_size)
{
    const float* rois   = nullptr;
    const float* probs  = nullptr;
    const float* deltas = nullptr;
    const float* window = nullptr;
    for (int i = 0; i < n_in; ++i) {
        switch (in_sizes[i]) {
            case BATCH * N_ROIS * 4:                rois   = (const float*)d_in[i]; break;
            case BATCH * N_ROIS * NUM_CLASSES:      probs  = (const float*)d_in[i]; break;
            case BATCH * N_ROIS * NUM_CLASSES * 4:  deltas = (const float*)d_in[i]; break;
            case BATCH * 4:                         window = (const float*)d_in[i]; break;
        }
    }
    det_fused_kernel<<<dim3(BATCH, NB_Y), 1024>>>(
        probs, rois, deltas, window, (float*)d_out);
}